// round 1
// baseline (speedup 1.0000x reference)
#include <cuda_runtime.h>
#include <cuda_bf16.h>

#define DMODEL 512
#define NHEAD 8
#define HDIM 64

#define MAX_T 4096

// Scratch buffers (no allocation allowed; __device__ globals are the sanctioned path)
__device__ float g_Q[MAX_T * DMODEL];
__device__ float g_K[MAX_T * DMODEL];
__device__ float g_V[MAX_T * DMODEL];
__device__ float g_O[MAX_T * DMODEL];

// ---------------------------------------------------------------------------
// Generic projection GEMM: C[T,512] = (A (+ P)) @ W + bias
// BM=64, BN=64, BK=16, 256 threads, 4x4 microtile per thread.
// A row-major [T,512], W row-major [512,512] (W[d_in][d_out]).
// ---------------------------------------------------------------------------
__global__ void gemm_proj(const float* __restrict__ A, const float* __restrict__ P,
                          const float* __restrict__ W, const float* __restrict__ bias,
                          float* __restrict__ C, int T)
{
    __shared__ float As[16][64];   // As[k][m]  (transposed)
    __shared__ float Bs[16][64];   // Bs[k][n]

    const int tid = threadIdx.x;            // 0..255
    const int tx = tid & 15;                // n direction
    const int ty = tid >> 4;                // m direction
    const int row0 = blockIdx.x * 64;
    const int col0 = blockIdx.y * 64;

    float acc[4][4] = {};

    for (int k0 = 0; k0 < DMODEL; k0 += 16) {
        // Load A tile (64 rows x 16 k) transposed into As[k][m]
        {
            const int r = tid >> 2;         // 0..63
            const int c = (tid & 3) * 4;    // 0,4,8,12
            float4 av = *(const float4*)&A[(size_t)(row0 + r) * DMODEL + k0 + c];
            if (P) {
                float4 pv = *(const float4*)&P[(size_t)(row0 + r) * DMODEL + k0 + c];
                av.x += pv.x; av.y += pv.y; av.z += pv.z; av.w += pv.w;
            }
            As[c + 0][r] = av.x;
            As[c + 1][r] = av.y;
            As[c + 2][r] = av.z;
            As[c + 3][r] = av.w;
        }
        // Load W tile (16 k x 64 n) into Bs[k][n]
        {
            const int r = tid >> 4;         // 0..15
            const int c = (tid & 15) * 4;   // 0..60
            *(float4*)&Bs[r][c] = *(const float4*)&W[(size_t)(k0 + r) * DMODEL + col0 + c];
        }
        __syncthreads();

#pragma unroll
        for (int kk = 0; kk < 16; kk++) {
            float4 a4 = *(const float4*)&As[kk][ty * 4];
            float4 b4 = *(const float4*)&Bs[kk][tx * 4];
            float af[4] = {a4.x, a4.y, a4.z, a4.w};
            float bf[4] = {b4.x, b4.y, b4.z, b4.w};
#pragma unroll
            for (int i = 0; i < 4; i++)
#pragma unroll
                for (int j = 0; j < 4; j++)
                    acc[i][j] += af[i] * bf[j];
        }
        __syncthreads();
    }

#pragma unroll
    for (int i = 0; i < 4; i++) {
        const int r = row0 + ty * 4 + i;
        float4 out;
        const int c = col0 + tx * 4;
        out.x = acc[i][0] + bias[c + 0];
        out.y = acc[i][1] + bias[c + 1];
        out.z = acc[i][2] + bias[c + 2];
        out.w = acc[i][3] + bias[c + 3];
        *(float4*)&C[(size_t)r * DMODEL + c] = out;
    }
}

// ---------------------------------------------------------------------------
// Block-diagonal flash attention.
// grid: (num_q_tiles_upper_bound, NHEAD); 256 threads (16x16).
// Each block: one 64-query tile inside one segment, one head.
// Smem: Qs[d][q] 64x64, Ks[d][k] 64x64, Vs[k][hd] 64x64, Ps[q][k] 64x64.
// ---------------------------------------------------------------------------
#define ATTN_SMEM (4 * 64 * 64 * sizeof(float))

__global__ void attn_kernel(const float* __restrict__ Q, const float* __restrict__ K,
                            const float* __restrict__ V, float* __restrict__ O,
                            const int* __restrict__ channels, int nseg, int T)
{
    // Derive segment layout from channels
    int csum = 0;
    for (int i = 0; i < nseg; i++) csum += channels[i];
    const int Stok = T / csum;   // tokens per channel (196)

    const int tile = blockIdx.x;
    const int h = blockIdx.y;

    int seg_start = 0, seg_len = 0, t_in_seg = -1;
    {
        int toff = 0, soff = 0;
        for (int i = 0; i < nseg; i++) {
            int L = channels[i] * Stok;
            int nt = (L + 63) >> 6;
            if (tile < toff + nt) { t_in_seg = tile - toff; seg_start = soff; seg_len = L; break; }
            toff += nt; soff += L;
        }
    }
    if (t_in_seg < 0) return;   // oversized grid tail

    const int q0 = seg_start + t_in_seg * 64;
    const int qlen = min(64, seg_len - t_in_seg * 64);

    extern __shared__ float sm[];
    float* Qs = sm;                 // [d][q] 64x64
    float* Ks = sm + 64 * 64;       // [d][k] 64x64
    float* Vs = sm + 2 * 64 * 64;   // [k][hd] 64x64
    float* Ps = sm + 3 * 64 * 64;   // [q][k] 64x64

    const int tid = threadIdx.x;
    const int tx = tid & 15;        // k / hd direction
    const int ty = tid >> 4;        // q direction

    // Load Q tile transposed: Qs[d][q]
    {
        const int r = tid >> 2;                 // token in tile
        const int dbase = (tid & 3) * 16;       // 16 d per thread
        const float* Qg = Q + (size_t)(q0 + r) * DMODEL + h * HDIM;
#pragma unroll
        for (int v = 0; v < 4; v++) {
            int d = dbase + v * 4;
            float4 qv = make_float4(0.f, 0.f, 0.f, 0.f);
            if (r < qlen) qv = *(const float4*)&Qg[d];
            Qs[(d + 0) * 64 + r] = qv.x;
            Qs[(d + 1) * 64 + r] = qv.y;
            Qs[(d + 2) * 64 + r] = qv.z;
            Qs[(d + 3) * 64 + r] = qv.w;
        }
    }

    float m_i[4], l_i[4], o[4][4];
#pragma unroll
    for (int i = 0; i < 4; i++) {
        m_i[i] = -1e30f; l_i[i] = 0.f;
#pragma unroll
        for (int j = 0; j < 4; j++) o[i][j] = 0.f;
    }

    const int nkt = (seg_len + 63) >> 6;
    const float scale = 0.125f;   // 1/sqrt(64)

    for (int kt = 0; kt < nkt; kt++) {
        const int k0 = seg_start + kt * 64;
        const int klen = min(64, seg_len - kt * 64);

        __syncthreads();   // previous iteration done reading Ks/Vs/Ps

        // Load K transposed: Ks[d][k]; load V natural: Vs[k][hd]
        {
            const int r = tid >> 2;
            const int dbase = (tid & 3) * 16;
            const float* Kg = K + (size_t)(k0 + r) * DMODEL + h * HDIM;
            const float* Vg = V + (size_t)(k0 + r) * DMODEL + h * HDIM;
#pragma unroll
            for (int v = 0; v < 4; v++) {
                int d = dbase + v * 4;
                float4 kv = make_float4(0.f, 0.f, 0.f, 0.f);
                float4 vv = make_float4(0.f, 0.f, 0.f, 0.f);
                if (r < klen) { kv = *(const float4*)&Kg[d]; vv = *(const float4*)&Vg[d]; }
                Ks[(d + 0) * 64 + r] = kv.x;
                Ks[(d + 1) * 64 + r] = kv.y;
                Ks[(d + 2) * 64 + r] = kv.z;
                Ks[(d + 3) * 64 + r] = kv.w;
                *(float4*)&Vs[r * 64 + d] = vv;
            }
        }
        __syncthreads();

        // Scores: s[i][j] = sum_d Qs[d][ty*4+i] * Ks[d][tx*4+j]
        float s[4][4] = {};
#pragma unroll 8
        for (int d = 0; d < 64; d++) {
            float4 q4 = *(const float4*)&Qs[d * 64 + ty * 4];
            float4 k4 = *(const float4*)&Ks[d * 64 + tx * 4];
            float qf[4] = {q4.x, q4.y, q4.z, q4.w};
            float kf[4] = {k4.x, k4.y, k4.z, k4.w};
#pragma unroll
            for (int i = 0; i < 4; i++)
#pragma unroll
                for (int j = 0; j < 4; j++)
                    s[i][j] += qf[i] * kf[j];
        }

        // Scale + mask invalid keys
#pragma unroll
        for (int i = 0; i < 4; i++)
#pragma unroll
            for (int j = 0; j < 4; j++) {
                s[i][j] *= scale;
                if (tx * 4 + j >= klen) s[i][j] = -1e30f;
            }

        // Online softmax per row (row = (ty,i); reduce across 16 tx lanes)
#pragma unroll
        for (int i = 0; i < 4; i++) {
            float mx = fmaxf(fmaxf(s[i][0], s[i][1]), fmaxf(s[i][2], s[i][3]));
#pragma unroll
            for (int off = 8; off >= 1; off >>= 1)
                mx = fmaxf(mx, __shfl_xor_sync(0xffffffffu, mx, off));
            float mnew = fmaxf(m_i[i], mx);
            float alpha = __expf(m_i[i] - mnew);
            m_i[i] = mnew;

            float4 p4;
            p4.x = __expf(s[i][0] - mnew);
            p4.y = __expf(s[i][1] - mnew);
            p4.z = __expf(s[i][2] - mnew);
            p4.w = __expf(s[i][3] - mnew);

            float rs = p4.x + p4.y + p4.z + p4.w;
#pragma unroll
            for (int off = 8; off >= 1; off >>= 1)
                rs += __shfl_xor_sync(0xffffffffu, rs, off);
            l_i[i] = l_i[i] * alpha + rs;

#pragma unroll
            for (int j = 0; j < 4; j++) o[i][j] *= alpha;

            *(float4*)&Ps[(ty * 4 + i) * 64 + tx * 4] = p4;
        }
        __syncthreads();

        // o += P @ V : o[i][j] += sum_k Ps[qr][k] * Vs[k][tx*4+j]
#pragma unroll 8
        for (int kk = 0; kk < 64; kk++) {
            float4 v4 = *(const float4*)&Vs[kk * 64 + tx * 4];
            float vf[4] = {v4.x, v4.y, v4.z, v4.w};
#pragma unroll
            for (int i = 0; i < 4; i++) {
                float pq = Ps[(ty * 4 + i) * 64 + kk];
#pragma unroll
                for (int j = 0; j < 4; j++)
                    o[i][j] += pq * vf[j];
            }
        }
    }

    // Normalize and store
#pragma unroll
    for (int i = 0; i < 4; i++) {
        const int qr = ty * 4 + i;
        if (qr < qlen) {
            float inv = 1.0f / l_i[i];
            float4 out;
            out.x = o[i][0] * inv;
            out.y = o[i][1] * inv;
            out.z = o[i][2] * inv;
            out.w = o[i][3] * inv;
            *(float4*)&O[(size_t)(q0 + qr) * DMODEL + h * HDIM + tx * 4] = out;
        }
    }
}

// ---------------------------------------------------------------------------
extern "C" void kernel_launch(void* const* d_in, const int* in_sizes, int n_in,
                              void* d_out, int out_size)
{
    const float* xq  = (const float*)d_in[0];
    const float* xk  = (const float*)d_in[1];
    const float* pos = (const float*)d_in[2];
    const int* channels = (const int*)d_in[3];
    const float* Wq = (const float*)d_in[4];  const float* bq = (const float*)d_in[5];
    const float* Wk = (const float*)d_in[6];  const float* bk = (const float*)d_in[7];
    const float* Wv = (const float*)d_in[8];  const float* bv = (const float*)d_in[9];
    const float* Wo = (const float*)d_in[10]; const float* bo = (const float*)d_in[11];

    const int T = in_sizes[0] / DMODEL;     // 3136
    const int nseg = in_sizes[3];           // 4

    float *pQ, *pK, *pV, *pO;
    cudaGetSymbolAddress((void**)&pQ, g_Q);
    cudaGetSymbolAddress((void**)&pK, g_K);
    cudaGetSymbolAddress((void**)&pV, g_V);
    cudaGetSymbolAddress((void**)&pO, g_O);

    dim3 blk(256);
    dim3 grd(T / 64, DMODEL / 64);

    gemm_proj<<<grd, blk>>>(xq, pos, Wq, bq, pQ, T);
    gemm_proj<<<grd, blk>>>(xk, pos, Wk, bk, pK, T);
    gemm_proj<<<grd, blk>>>(xk, nullptr, Wv, bv, pV, T);

    cudaFuncSetAttribute(attn_kernel, cudaFuncAttributeMaxDynamicSharedMemorySize,
                         (int)ATTN_SMEM);
    dim3 agrd(T / 64 + nseg, NHEAD);
    attn_kernel<<<agrd, blk, ATTN_SMEM>>>(pQ, pK, pV, pO, channels, nseg, T);

    gemm_proj<<<grd, blk>>>(pO, nullptr, Wo, bo, (float*)d_out, T);
}